// round 9
// baseline (speedup 1.0000x reference)
#include <cuda_runtime.h>

#define BB 256
#define TT 50
#define MM 20
#define EE 128
#define G3 384

typedef unsigned long long u64;

// scratch (no cudaMalloc allowed)
__device__ __align__(16) float g_ub[BB*TT*EE];   // basket means (B,T,E)

__device__ __forceinline__ void fma2(u64 &acc, u64 a, u64 b){
    asm("fma.rn.f32x2 %0, %1, %2, %0;" : "+l"(acc) : "l"(a), "l"(b));
}
__device__ __forceinline__ float hsum2(u64 v){
    float lo, hi;
    asm("mov.b64 {%0,%1}, %2;" : "=f"(lo), "=f"(hi) : "l"(v));
    return lo + hi;
}
__device__ __forceinline__ float sigf(float x){
    return __fdividef(1.f, 1.f + __expf(-x));
}
__device__ __forceinline__ float tanhfast(float x){
    return __fdividef(2.f, 1.f + __expf(-2.f*x)) - 1.f;
}
__device__ __forceinline__ int zero_dep(float x){
    int r;
    asm("{\n\t.reg .b32 t;\n\tmov.b32 t, %1;\n\tand.b32 %0, t, 0;\n\t}"
        : "=r"(r) : "f"(x));
    return r;
}
__device__ __forceinline__ float qreduce(float f){
    f += __shfl_xor_sync(0xFFFFFFFFu, f, 1);
    f += __shfl_xor_sync(0xFFFFFFFFu, f, 2);
    return f;
}

// ---------------------------------------------------------------------------
// Layout: thread (e = j>>2, kq = j&3) owns W rows {e, e+128, e+256} (the
// r/z/n rows of element e), K-quarter [kq*32, kq*32+32). Quarter iteration
// order rotated by 2*kq -> the 4 quarters of a warp hit disjoint bank groups.
// ---------------------------------------------------------------------------
__device__ __forceinline__ void load_w(u64 w[3][16], const float* __restrict__ W,
                                       int e, int kq, int dep){
    #pragma unroll
    for (int m = 0; m < 3; ++m){
        const u64* wb = (const u64*)(W + (e + 128*m + dep)*EE + kq*32);
        #pragma unroll
        for (int i = 0; i < 8; ++i){
            const int o = ((i + 2*kq) & 7) * 2;
            w[m][2*i]   = __ldg(wb + o);
            w[m][2*i+1] = __ldg(wb + o + 1);
        }
    }
}

__device__ __forceinline__ void dot3_s(const u64 w[3][16],
                                       const float* __restrict__ src, int kq,
                                       float &f0, float &f1, float &f2){
    u64 a0=0ull, a1=0ull, a2=0ull;
    const ulonglong2* hp = (const ulonglong2*)(src + kq*32);
    #pragma unroll
    for (int i = 0; i < 8; ++i){
        const int ii = (i + 2*kq) & 7;
        ulonglong2 v = hp[ii];
        fma2(a0, w[0][2*i], v.x); fma2(a0, w[0][2*i+1], v.y);
        fma2(a1, w[1][2*i], v.x); fma2(a1, w[1][2*i+1], v.y);
        fma2(a2, w[2][2*i], v.x); fma2(a2, w[2][2*i+1], v.y);
    }
    f0 = qreduce(hsum2(a0));
    f1 = qreduce(hsum2(a1));
    f2 = qreduce(hsum2(a2));
}

__device__ __forceinline__ void dot3_g(const u64 w[3][16],
                                       const float* __restrict__ src, int kq,
                                       float &f0, float &f1, float &f2){
    u64 a0=0ull, a1=0ull, a2=0ull;
    const ulonglong2* hp = (const ulonglong2*)(src + kq*32);
    #pragma unroll
    for (int i = 0; i < 8; ++i){
        const int ii = (i + 2*kq) & 7;
        ulonglong2 v = __ldg(hp + ii);
        fma2(a0, w[0][2*i], v.x); fma2(a0, w[0][2*i+1], v.y);
        fma2(a1, w[1][2*i], v.x); fma2(a1, w[1][2*i+1], v.y);
        fma2(a2, w[2][2*i], v.x); fma2(a2, w[2][2*i+1], v.y);
    }
    f0 = qreduce(hsum2(a0));
    f1 = qreduce(hsum2(a1));
    f2 = qreduce(hsum2(a2));
}

// ---------------------------------------------------------------------------
// K1: gather (measured ~5us, unchanged)
// ---------------------------------------------------------------------------
#define RED20(FLD) \
    ((((v[0].FLD+v[1].FLD)+(v[2].FLD+v[3].FLD))+((v[4].FLD+v[5].FLD)+(v[6].FLD+v[7].FLD))) \
    +(((v[8].FLD+v[9].FLD)+(v[10].FLD+v[11].FLD))+((v[12].FLD+v[13].FLD)+(v[14].FLD+v[15].FLD))) \
    +((v[16].FLD+v[17].FLD)+(v[18].FLD+v[19].FLD)))

__global__ void __launch_bounds__(128,2) k_gather(const int* __restrict__ ids,
                                                  const int* __restrict__ bsz,
                                                  const int* __restrict__ lens,
                                                  const float* __restrict__ emb){
    const int p    = blockIdx.x * 4 + (threadIdx.x >> 5);   // 0..6399
    const int lane = threadIdx.x & 31;
    const float4* e4 = (const float4*)emb;

    const int r0 = p, r1 = 12799 - p;
    const int b0g = r0 / TT, t0g = r0 - b0g*TT;
    const int b1g = r1 / TT, t1g = r1 - b1g*TT;
    const bool act0 = t0g < __ldg(lens + b0g);
    const bool act1 = t1g < __ldg(lens + b1g);

    float4 v[20], u[20];
    if (act0){
        const int4* ip = (const int4*)(ids + r0*MM);
        const int4 i0=__ldg(ip), i1=__ldg(ip+1), i2=__ldg(ip+2),
                   i3=__ldg(ip+3), i4=__ldg(ip+4);
        v[0]=__ldg(e4+i0.x*32+lane);  v[1]=__ldg(e4+i0.y*32+lane);
        v[2]=__ldg(e4+i0.z*32+lane);  v[3]=__ldg(e4+i0.w*32+lane);
        v[4]=__ldg(e4+i1.x*32+lane);  v[5]=__ldg(e4+i1.y*32+lane);
        v[6]=__ldg(e4+i1.z*32+lane);  v[7]=__ldg(e4+i1.w*32+lane);
        v[8]=__ldg(e4+i2.x*32+lane);  v[9]=__ldg(e4+i2.y*32+lane);
        v[10]=__ldg(e4+i2.z*32+lane); v[11]=__ldg(e4+i2.w*32+lane);
        v[12]=__ldg(e4+i3.x*32+lane); v[13]=__ldg(e4+i3.y*32+lane);
        v[14]=__ldg(e4+i3.z*32+lane); v[15]=__ldg(e4+i3.w*32+lane);
        v[16]=__ldg(e4+i4.x*32+lane); v[17]=__ldg(e4+i4.y*32+lane);
        v[18]=__ldg(e4+i4.z*32+lane); v[19]=__ldg(e4+i4.w*32+lane);
    }
    if (act1){
        const int4* ip = (const int4*)(ids + r1*MM);
        const int4 i0=__ldg(ip), i1=__ldg(ip+1), i2=__ldg(ip+2),
                   i3=__ldg(ip+3), i4=__ldg(ip+4);
        u[0]=__ldg(e4+i0.x*32+lane);  u[1]=__ldg(e4+i0.y*32+lane);
        u[2]=__ldg(e4+i0.z*32+lane);  u[3]=__ldg(e4+i0.w*32+lane);
        u[4]=__ldg(e4+i1.x*32+lane);  u[5]=__ldg(e4+i1.y*32+lane);
        u[6]=__ldg(e4+i1.z*32+lane);  u[7]=__ldg(e4+i1.w*32+lane);
        u[8]=__ldg(e4+i2.x*32+lane);  u[9]=__ldg(e4+i2.y*32+lane);
        u[10]=__ldg(e4+i2.z*32+lane); u[11]=__ldg(e4+i2.w*32+lane);
        u[12]=__ldg(e4+i3.x*32+lane); u[13]=__ldg(e4+i3.y*32+lane);
        u[14]=__ldg(e4+i3.z*32+lane); u[15]=__ldg(e4+i3.w*32+lane);
        u[16]=__ldg(e4+i4.x*32+lane); u[17]=__ldg(e4+i4.y*32+lane);
        u[18]=__ldg(e4+i4.z*32+lane); u[19]=__ldg(e4+i4.w*32+lane);
    }
    if (act0){
        const float inv = 1.0f / (float)__ldg(bsz + r0);
        float4 a;
        a.x = RED20(x)*inv; a.y = RED20(y)*inv; a.z = RED20(z)*inv; a.w = RED20(w)*inv;
        ((float4*)g_ub)[r0*32 + lane] = a;
    }
    if (act1){
        #pragma unroll
        for (int k = 0; k < 20; ++k) v[k] = u[k];
        const float inv = 1.0f / (float)__ldg(bsz + r1);
        float4 a;
        a.x = RED20(x)*inv; a.y = RED20(y)*inv; a.z = RED20(z)*inv; a.w = RED20(w)*inv;
        ((float4*)g_ub)[r1*32 + lane] = a;
    }
}

// ---------------------------------------------------------------------------
// K2: fused xg + scan. 512 threads; gate-local (e,e+128,e+256) x K/4 layout.
// 1 barrier per scan step (double-buffered h; inline gates after shfl reduce).
// SMEM: xg 2*50*384 + h 2*2*128 = 38912 floats = 155648 B
// ---------------------------------------------------------------------------
__global__ void __launch_bounds__(512,1) k_xgscan(
    const float* __restrict__ W_ih,
    const float* __restrict__ W_hh,
    const float* __restrict__ b_ih,
    const float* __restrict__ b_hh,
    const float* __restrict__ h0,
    const int*   __restrict__ lens,
    float*       __restrict__ out)
{
    extern __shared__ float smem[];
    float* s_xg = smem;                    // [2][TT][G3]
    float* s_h  = s_xg + 2*TT*G3;          // [2 buf][2 rows][EE]

    const int j  = threadIdx.x;
    const int e  = j >> 2, kq = j & 3;
    const int b0 = blockIdx.x, b1 = (BB-1) - blockIdx.x;
    const int len0 = __ldg(lens + b0), len1 = __ldg(lens + b1);
    const int total = len0 + len1;
    const int maxlen = max(len0, len1);

    u64 w[3][16];

    // ---------------- Phase B: xg -> SMEM (barrier-free) ----------------
    // fold b_ih (all rows) + b_hh (r,z rows only) into s_xg; b_hh(n) kept.
    load_w(w, W_ih, e, kq, 0);
    {
        const float c0 = __ldg(b_ih + e)       + __ldg(b_hh + e);
        const float c1 = __ldg(b_ih + e + 128) + __ldg(b_hh + e + 128);
        const float c2 = __ldg(b_ih + e + 256);
        for (int i = 0; i < total; ++i){
            const int row = (i >= len0);
            const int t   = row ? i - len0 : i;
            const float* src = g_ub + ((row ? b1 : b0)*TT + t)*EE;
            float f0, f1, f2;
            dot3_g(w, src, kq, f0, f1, f2);
            if (kq == 0){
                float* dst = s_xg + (row*TT + t)*G3;
                dst[e]       = f0 + c0;
                dst[e + 128] = f1 + c1;
                dst[e + 256] = f2 + c2;
            }
        }
    }
    if (j < EE){
        s_h[j]      = __ldg(h0 + b0*EE + j);
        s_h[EE + j] = __ldg(h0 + b1*EE + j);
    }
    __syncthreads();

    // ---------------- Phase C: scan ----------------
    const int dep = zero_dep(s_xg[j]);     // keep W_hh loads after phase B
    load_w(w, W_hh, e, kq, dep);
    const float bhn = __ldg(b_hh + e + 256);

    for (int t = 0; t < maxlen; ++t){
        const int  cur = (t & 1) * 2*EE, nxt = cur ^ (2*EE);
        const bool a0 = (t < len0), a1 = (t < len1);

        float f0, f1, f2, g0, g1, g2;
        if (a0) dot3_s(w, s_h + cur,      kq, f0, f1, f2);
        if (a1) dot3_s(w, s_h + cur + EE, kq, g0, g1, g2);

        if (kq == 0){
            if (a0){
                const float* xr = s_xg + t*G3;
                const float r  = sigf(xr[e]       + f0);
                const float z  = sigf(xr[e + 128] + f1);
                const float n  = tanhfast(xr[e + 256] + r*(f2 + bhn));
                const float hv = (1.f - z)*n + z * s_h[cur + e];
                s_h[nxt + e] = hv;
                out[(b0*TT + t)*EE + e] = hv;
            } else {
                s_h[nxt + e] = s_h[cur + e];
            }
            if (a1){
                const float* xr = s_xg + (TT + t)*G3;
                const float r  = sigf(xr[e]       + g0);
                const float z  = sigf(xr[e + 128] + g1);
                const float n  = tanhfast(xr[e + 256] + r*(g2 + bhn));
                const float hv = (1.f - z)*n + z * s_h[cur + EE + e];
                s_h[nxt + EE + e] = hv;
                out[(b1*TT + t)*EE + e] = hv;
            } else {
                s_h[nxt + EE + e] = s_h[cur + EE + e];
            }
        }
        __syncthreads();
    }

    // ---------------- epilogue: masked tail zeros + h_u ----------------
    {
        const float4 z4 = make_float4(0.f, 0.f, 0.f, 0.f);
        float4* p0 = (float4*)(out + (b0*TT + len0)*EE);
        const int n0 = (TT - len0) * (EE/4);
        for (int k = j; k < n0; k += 512) p0[k] = z4;
        float4* p1 = (float4*)(out + (b1*TT + len1)*EE);
        const int n1 = (TT - len1) * (EE/4);
        for (int k = j; k < n1; k += 512) p1[k] = z4;
    }
    {
        const int fin = (maxlen & 1) * 2*EE;
        if (j < EE){
            out[BB*TT*EE + b0*EE + j] = s_h[fin + j];
            out[BB*TT*EE + b1*EE + j] = s_h[fin + EE + j];
        }
    }
}

// ---------------------------------------------------------------------------
extern "C" void kernel_launch(void* const* d_in, const int* in_sizes, int n_in,
                              void* d_out, int out_size){
    const int*   item_ids = (const int*)  d_in[0];
    const int*   bsz      = (const int*)  d_in[1];
    const int*   lengths  = (const int*)  d_in[2];
    const float* emb      = (const float*)d_in[3];
    const float* W_ih     = (const float*)d_in[4];
    const float* W_hh     = (const float*)d_in[5];
    const float* b_ih     = (const float*)d_in[6];
    const float* b_hh     = (const float*)d_in[7];
    const float* h0       = (const float*)d_in[8];
    float* out = (float*)d_out;

    const int smem_bytes = (2*TT*G3 + 4*EE) * 4;   // 155648
    cudaFuncSetAttribute(k_xgscan, cudaFuncAttributeMaxDynamicSharedMemorySize,
                         smem_bytes);

    k_gather<<<1600, 128>>>(item_ids, bsz, lengths, emb);
    k_xgscan<<<BB/2, 512, smem_bytes>>>(W_ih, W_hh, b_ih, b_hh, h0,
                                        lengths, out);
}